// round 3
// baseline (speedup 1.0000x reference)
#include <cuda_runtime.h>
#include <stdint.h>

#define NB 8
#define NANCH 13343
#define TOPK 1000
#define CAND 2048
#define NCLS 80
#define NPF 128   // prefetched mask rows in k_scan

// ---------------- scratch (device globals; no allocation allowed) ----------------
__device__ unsigned g_sbits[NB * NANCH];
__device__ int      g_cls[NB * NANCH];
__device__ float    g_bx1[NB * NANCH], g_by1[NB * NANCH], g_bx2[NB * NANCH], g_by2[NB * NANCH];

__device__ float    g_tsc[NB * 1024];
__device__ int      g_tcl[NB * 1024];
__device__ float    g_tx1[NB * 1024], g_ty1[NB * 1024], g_tx2[NB * 1024], g_ty2[NB * 1024];
__device__ float    g_ox1[NB * 1024], g_oy1[NB * 1024], g_ox2[NB * 1024], g_oy2[NB * 1024], g_oar[NB * 1024];

__device__ unsigned      g_mask[NB * TOPK * 32];
__device__ unsigned char g_rnz[NB * TOPK];

struct Ptrs {
    const float* cls[5];
    const float* cnt[5];
    const float* reg[5];
};

// ---------------- XLA-compatible sigmoid (fma-free Horner, verified R2) ----------------
__device__ __forceinline__ float xla_tanh(float x) {
    float xc = fminf(fmaxf(x, -7.90531110763549805f), 7.90531110763549805f);
    float x2 = __fmul_rn(xc, xc);
    float p = -2.76076847742355e-16f;
    p = __fadd_rn(__fmul_rn(p, x2), 2.00018790482477e-13f);
    p = __fadd_rn(__fmul_rn(p, x2), -8.60467152213735e-11f);
    p = __fadd_rn(__fmul_rn(p, x2), 5.12229709037114e-08f);
    p = __fadd_rn(__fmul_rn(p, x2), 1.48572235717979e-05f);
    p = __fadd_rn(__fmul_rn(p, x2), 6.37261928875436e-04f);
    p = __fadd_rn(__fmul_rn(p, x2), 4.89352455891786e-03f);
    p = __fmul_rn(xc, p);
    float q = 1.19825839466702e-06f;
    q = __fadd_rn(__fmul_rn(q, x2), 1.18534705686654e-04f);
    q = __fadd_rn(__fmul_rn(q, x2), 2.26843463243900e-03f);
    q = __fadd_rn(__fmul_rn(q, x2), 4.89352518554385e-03f);
    float r = __fdiv_rn(p, q);
    return (fabsf(x) < 0.0004f) ? x : r;
}
__device__ __forceinline__ float xla_sigmoid(float x) {
    return __fadd_rn(0.5f, __fmul_rn(0.5f, xla_tanh(__fmul_rn(0.5f, x))));
}

// ---------------- kernel 1: per-anchor scores / classes / boxes ----------------
// argmax over sigmoid == argmax over logits (monotone). Track top-2 logits and
// apply exact JAX first-occurrence semantics on their sigmoids (covers float
// ties AND any 1-ulp non-monotonicity of the rational tanh).
__global__ void k_score(Ptrs P) {
    int t = blockIdx.x * blockDim.x + threadIdx.x;
    if (t >= NB * NANCH) return;
    int b = t / NANCH;
    int a = t - b * NANCH;

    int l, p;
    if (a < 10000)      { l = 0; p = a; }
    else if (a < 12500) { l = 1; p = a - 10000; }
    else if (a < 13125) { l = 2; p = a - 12500; }
    else if (a < 13294) { l = 3; p = a - 13125; }
    else                { l = 4; p = a - 13294; }

    const int wlv[5] = {100, 50, 25, 13, 7};
    const int hwv[5] = {10000, 2500, 625, 169, 49};
    const int stv[5] = {8, 16, 32, 64, 128};
    int w = wlv[l], HW = hwv[l], s = stv[l];
    int y = p / w, x = p - y * w;
    float cx = (float)(x * s + (s >> 1));
    float cy = (float)(y * s + (s >> 1));

    const float* cls = P.cls[l];
    const float* cnt = P.cnt[l];
    const float* reg = P.reg[l];

    float ninf = -__int_as_float(0x7f800000);
    float m1 = ninf, m2 = ninf;
    int i1 = 0, i2 = 0;
    const float* cp = cls + (size_t)b * NCLS * HW + p;
#pragma unroll 8
    for (int c = 0; c < NCLS; c++) {
        float v = __ldg(cp + (size_t)c * HW);
        if (v > m1) { m2 = m1; i2 = i1; m1 = v; i1 = c; }
        else if (v > m2) { m2 = v; i2 = c; }
    }
    float s1 = xla_sigmoid(m1);
    float s2 = xla_sigmoid(m2);
    float best = s1;
    int bi = i1;
    if (s2 > s1 || (s2 == s1 && i2 < i1)) {
        best = fmaxf(s1, s2);   // s2 >= s1 in both branches
        bi = i2;
    }
    float cv = xla_sigmoid(__ldg(cnt + (size_t)b * HW + p));
    float score = sqrtf(__fmul_rn(best, cv));

    int o = b * NANCH + a;
    g_sbits[o] = __float_as_uint(score);
    g_cls[o] = bi + 1;

    float r0 = __ldg(reg + ((size_t)b * 4 + 0) * HW + p);
    float r1 = __ldg(reg + ((size_t)b * 4 + 1) * HW + p);
    float r2 = __ldg(reg + ((size_t)b * 4 + 2) * HW + p);
    float r3 = __ldg(reg + ((size_t)b * 4 + 3) * HW + p);
    g_bx1[o] = __fsub_rn(cx, r0);
    g_by1[o] = __fsub_rn(cy, r1);
    g_bx2[o] = __fadd_rn(cx, r2);
    g_by2[o] = __fadd_rn(cy, r3);
}

// ---------------- kernel 2: per-batch exact top-1000 (radix select + rank-by-count) ----------------
__global__ __launch_bounds__(1024) void k_topk() {
    __shared__ unsigned s_hist[1024];
    __shared__ unsigned s_wsum[32];
    __shared__ unsigned long long s_cand[CAND];
    __shared__ unsigned s_B, s_above, s_cnt;
    __shared__ float s_red[32];
    __shared__ float s_max;

    int b = blockIdx.x;
    int tid = threadIdx.x;
    int lane = tid & 31, wid = tid >> 5;
    const unsigned* sb = g_sbits + b * NANCH;

    // 3-pass 10-bit radix on positive-float bits -> bits of the 1000th-largest.
    unsigned prefix = 0;
    unsigned target = TOPK;
    for (int pass = 0; pass < 3; pass++) {
        int shift = 20 - 10 * pass;
        s_hist[tid] = 0;
        __syncthreads();
        for (int i = tid; i < NANCH; i += 1024) {
            unsigned v = sb[i];
            bool in = (pass == 0) || ((v >> (shift + 10)) == prefix);
            if (in) atomicAdd(&s_hist[(v >> shift) & 1023], 1u);
        }
        __syncthreads();
        unsigned h = s_hist[tid];
        // inclusive suffix sum: warp-shuffle within warp, then cross-warp.
        unsigned v = h;
#pragma unroll
        for (int off = 1; off < 32; off <<= 1) {
            unsigned u = __shfl_down_sync(0xffffffffu, v, off);
            if (lane + off < 32) v += u;
        }
        if (lane == 0) s_wsum[wid] = v;   // sum of this warp's 32 bins
        __syncthreads();
        if (tid < 32) {
            unsigned wv = s_wsum[tid];
            unsigned excl = 0;            // sum of warp totals AFTER warp tid
#pragma unroll
            for (int off = 1; off < 32; off <<= 1) {
                unsigned u = __shfl_down_sync(0xffffffffu, wv + excl, 0); (void)u;
                break;
            }
            // simple exclusive suffix via shuffles:
            unsigned acc = wv;
#pragma unroll
            for (int off = 1; off < 32; off <<= 1) {
                unsigned u = __shfl_down_sync(0xffffffffu, acc, off);
                if (tid + off < 32) acc += u;
            }
            s_wsum[tid] = acc - wv;       // exclusive suffix of warp totals
        }
        __syncthreads();
        unsigned S = v + s_wsum[wid];     // inclusive suffix over all 1024 bins
        unsigned nxt = S - h;             // suffix starting at bin tid+1
        if (S >= target && nxt < target) { s_B = tid; s_above = nxt; }
        __syncthreads();
        prefix = (prefix << 10) | s_B;
        target = target - s_above;
        __syncthreads();
    }
    unsigned T = prefix;  // threshold bit pattern

    // gather candidates (bits >= T): count >= 1000 by construction, ~= 1000.
    if (tid == 0) s_cnt = 0;
    __syncthreads();
    for (int i = tid; i < NANCH; i += 1024) {
        unsigned v = sb[i];
        if (v >= T) {
            unsigned pos = atomicAdd(&s_cnt, 1u);
            if (pos < CAND)
                s_cand[pos] = ((unsigned long long)v << 32) | (unsigned)(~i);
        }
    }
    __syncthreads();
    int n = (int)min(s_cnt, (unsigned)CAND);

    // rank-by-count: rank = #(keys > mine). Keys distinct (idx unique), ties in
    // score break by smaller idx (larger ~idx) == jax.lax.top_k stable order.
    unsigned long long k1 = 0, k2 = 0;
    bool h1 = (tid < n), h2 = (tid + 1024 < n);
    if (h1) k1 = s_cand[tid];
    if (h2) k2 = s_cand[tid + 1024];
    int r1 = 0, r2 = 0;
    for (int j = 0; j < n; j++) {
        unsigned long long kj = s_cand[j];   // broadcast
        r1 += (kj > k1);
        r2 += (kj > k2);
    }

    // per-candidate epilogue phase 1: gather + stage, accumulate max_coord
    float mloc = -__int_as_float(0x7f800000);
    float csc[2], cx1[2], cy1[2], cx2[2], cy2[2];
    int ccl[2], crk[2];
    bool act[2];
#pragma unroll
    for (int rp = 0; rp < 2; rp++) {
        unsigned long long key = rp ? k2 : k1;
        int rk = rp ? r2 : r1;
        bool on = (rp ? h2 : h1) && (rk < TOPK);
        act[rp] = on; crk[rp] = rk;
        csc[rp] = 0.f; ccl[rp] = 0; cx1[rp] = cy1[rp] = cx2[rp] = cy2[rp] = 0.f;
        if (on) {
            unsigned sbits = (unsigned)(key >> 32);
            int idx = (int)(~(unsigned)key);
            float sc = __uint_as_float(sbits);
            int o = b * NANCH + idx;
            int cl = g_cls[o];
            float x1 = g_bx1[o], y1 = g_by1[o], x2 = g_bx2[o], y2 = g_by2[o];
            csc[rp] = sc; ccl[rp] = cl;
            cx1[rp] = x1; cy1[rp] = y1; cx2[rp] = x2; cy2[rp] = y2;
            int to = b * 1024 + rk;
            g_tsc[to] = sc; g_tcl[to] = cl;
            g_tx1[to] = x1; g_ty1[to] = y1; g_tx2[to] = x2; g_ty2[to] = y2;
            bool valid = (sc >= 0.05f);
            float m = valid ? fmaxf(fmaxf(x1, y1), fmaxf(x2, y2)) : 0.0f;
            mloc = fmaxf(mloc, m);
        }
    }
    // block max-reduce
    float m = mloc;
#pragma unroll
    for (int o = 16; o > 0; o >>= 1) m = fmaxf(m, __shfl_down_sync(0xffffffffu, m, o));
    if (lane == 0) s_red[wid] = m;
    __syncthreads();
    if (tid < 32) {
        float v = s_red[tid];
#pragma unroll
        for (int o = 16; o > 0; o >>= 1) v = fmaxf(v, __shfl_down_sync(0xffffffffu, v, o));
        if (tid == 0) s_max = v;
    }
    __syncthreads();
    float maxc = s_max;

    // phase 2: offset boxes + areas
#pragma unroll
    for (int rp = 0; rp < 2; rp++) {
        if (act[rp]) {
            float off = __fmul_rn((float)ccl[rp], __fadd_rn(maxc, 1.0f));
            float ox1 = __fadd_rn(cx1[rp], off);
            float oy1 = __fadd_rn(cy1[rp], off);
            float ox2 = __fadd_rn(cx2[rp], off);
            float oy2 = __fadd_rn(cy2[rp], off);
            float area = __fmul_rn(__fadd_rn(__fsub_rn(ox2, ox1), 1.0f),
                                   __fadd_rn(__fsub_rn(oy2, oy1), 1.0f));
            int to = b * 1024 + crk[rp];
            g_ox1[to] = ox1; g_oy1[to] = oy1; g_ox2[to] = ox2; g_oy2[to] = oy2;
            g_oar[to] = area;
        }
    }
}

// ---------------- kernel 3a: suppression bitmask, smem-tiled per batch ----------------
__global__ __launch_bounds__(256) void k_mask() {
    __shared__ float sx1[TOPK], sy1[TOPK], sx2[TOPK], sy2[TOPK], sar[TOPK];
    int b = blockIdx.y;
    int tid = threadIdx.x;
    int lane = tid & 31, wrp = tid >> 5;
    int base = b * 1024;

    for (int idx = tid; idx < TOPK; idx += 256) {
        sx1[idx] = g_ox1[base + idx];
        sy1[idx] = g_oy1[base + idx];
        sx2[idx] = g_ox2[base + idx];
        sy2[idx] = g_oy2[base + idx];
        sar[idx] = g_oar[base + idx];
    }
    __syncthreads();

    int i = blockIdx.x * 8 + wrp;   // 125 * 8 = 1000 rows
    if (i >= TOPK) return;
    float x1i = sx1[i], y1i = sy1[i], x2i = sx2[i], y2i = sy2[i], ai = sar[i];

    unsigned rowor = 0;
#pragma unroll 4
    for (int w = 0; w < 32; w++) {
        int j = w * 32 + lane;
        unsigned bit = 0;
        if (j > i && j < TOPK) {
            float xx1 = fmaxf(x1i, sx1[j]);
            float yy1 = fmaxf(y1i, sy1[j]);
            float xx2 = fminf(x2i, sx2[j]);
            float yy2 = fminf(y2i, sy2[j]);
            float iw = fmaxf(__fsub_rn(xx2, xx1), 0.0f);
            float ih = fmaxf(__fsub_rn(yy2, yy1), 0.0f);
            float inter = __fmul_rn(iw, ih);
            float uni = __fsub_rn(__fadd_rn(ai, sar[j]), inter);
            float iou = __fdiv_rn(inter, uni);
            bit = (iou > 0.6f) ? 1u : 0u;
        }
        unsigned word = __ballot_sync(0xffffffffu, bit);
        if (lane == 0) {
            g_mask[(b * TOPK + i) * 32 + w] = word;
            rowor |= word;
        }
    }
    if (lane == 0) g_rnz[b * TOPK + i] = (rowor != 0) ? 1 : 0;
}

// ---------------- kernel 3b: sparse greedy scan (smem-prefetched masks) + output ----------------
__global__ __launch_bounds__(256) void k_scan(float* out) {
    __shared__ unsigned s_valid[32], s_ne[32];
    __shared__ volatile unsigned s_removed[32];
    __shared__ unsigned s_pf[NPF][32];
    __shared__ short s_slot[TOPK];
    __shared__ short s_rowof[NPF];
    __shared__ unsigned s_nrows;

    int b = blockIdx.x;
    int tid = threadIdx.x;
    int lane = tid & 31;

    if (tid == 0) s_nrows = 0;
    if (tid < 32) s_removed[tid] = 0;

    for (int k = 0; k < 4; k++) {
        int t = k * 256 + tid;
        int v = 0, nz = 0;
        if (t < TOPK) {
            v = (g_tsc[b * 1024 + t] >= 0.05f) ? 1 : 0;
            nz = g_rnz[b * TOPK + t];
        }
        unsigned bv = __ballot_sync(0xffffffffu, v);
        unsigned bn = __ballot_sync(0xffffffffu, nz);
        if (lane == 0 && t < TOPK) { s_valid[t >> 5] = bv; s_ne[t >> 5] = bn; }
    }
    __syncthreads();

    // slot assignment for rows that the scan may visit (valid & nonempty)
    for (int k = 0; k < 4; k++) {
        int t = k * 256 + tid;
        if (t < TOPK) {
            bool need = (((s_valid[t >> 5] >> (t & 31)) & 1u) != 0u) &&
                        (((s_ne[t >> 5] >> (t & 31)) & 1u) != 0u);
            short slot = -1;
            if (need) {
                unsigned s = atomicAdd(&s_nrows, 1u);
                if (s < NPF) { slot = (short)s; s_rowof[s] = (short)t; }
            }
            s_slot[t] = slot;
        }
    }
    __syncthreads();

    // cooperative prefetch of those mask rows into smem (coalesced, 32 lanes/row)
    int nr = (int)min(s_nrows, (unsigned)NPF);
    for (int wdx = tid; wdx < nr * 32; wdx += 256) {
        int s = wdx >> 5, ln = wdx & 31;
        s_pf[s][ln] = g_mask[(b * TOPK + s_rowof[s]) * 32 + ln];
    }
    __syncthreads();

    // warp 0: greedy scan over valid & nonempty rows, ascending (rows only set bits j>i)
    if (tid < 32) {
        for (int w = 0; w < 32; ++w) {
            unsigned cand = s_valid[w] & s_ne[w];
            while (true) {
                unsigned rm = s_removed[w];
                unsigned act2 = cand & ~rm;
                if (!act2) break;
                int bp = __ffs(act2) - 1;
                cand &= ~(1u << bp);
                int i = w * 32 + bp;
                short slot = s_slot[i];
                unsigned mrow = (slot >= 0) ? s_pf[slot][lane]
                                            : g_mask[(b * TOPK + i) * 32 + lane];
                s_removed[lane] = s_removed[lane] | mrow;
                __syncwarp();
            }
        }
    }
    __syncthreads();

    // outputs: scores | classes | boxes
    for (int k = 0; k < 4; k++) {
        int t = k * 256 + tid;
        if (t < TOPK) {
            unsigned rem = s_removed[t >> 5];
            bool keep = (((s_valid[t >> 5] >> (t & 31)) & 1u) != 0u) &&
                        (((rem >> (t & 31)) & 1u) == 0u);
            int to = b * 1024 + t;
            float sc = keep ? g_tsc[to] : 0.0f;
            float cf = keep ? (float)g_tcl[to] : 0.0f;
            out[b * TOPK + t] = sc;
            out[NB * TOPK + b * TOPK + t] = cf;
            float bx1 = keep ? g_tx1[to] : 0.0f;
            float by1 = keep ? g_ty1[to] : 0.0f;
            float bx2 = keep ? g_tx2[to] : 0.0f;
            float by2 = keep ? g_ty2[to] : 0.0f;
            size_t bo = (size_t)2 * NB * TOPK + ((size_t)(b * TOPK + t)) * 4;
            out[bo + 0] = bx1;
            out[bo + 1] = by1;
            out[bo + 2] = bx2;
            out[bo + 3] = by2;
        }
    }
}

// ---------------- launch ----------------
extern "C" void kernel_launch(void* const* d_in, const int* in_sizes, int n_in,
                              void* d_out, int out_size) {
    (void)in_sizes; (void)n_in; (void)out_size;
    Ptrs P;
    for (int i = 0; i < 5; i++) {
        P.cls[i] = (const float*)d_in[i];
        P.cnt[i] = (const float*)d_in[5 + i];
        P.reg[i] = (const float*)d_in[10 + i];
    }
    int total = NB * NANCH;
    k_score<<<(total + 255) / 256, 256>>>(P);
    k_topk<<<NB, 1024>>>();
    dim3 mg(125, 8);
    k_mask<<<mg, 256>>>();
    k_scan<<<NB, 256>>>((float*)d_out);
}

// round 4
// speedup vs baseline: 1.5900x; 1.5900x over previous
#include <cuda_runtime.h>
#include <stdint.h>

#define NB 8
#define NANCH 13343
#define TOPK 1000
#define CAND 2048
#define NCLS 80
#define SEGW 128
#define NSEG 16   // SEGW * NSEG == CAND

// ---------------- scratch (device globals; no allocation allowed) ----------------
__device__ unsigned g_sbits[NB * NANCH];
__device__ int      g_cls[NB * NANCH];
__device__ float    g_bx1[NB * NANCH], g_by1[NB * NANCH], g_bx2[NB * NANCH], g_by2[NB * NANCH];

__device__ unsigned long long g_cand[NB * CAND];
__device__ int      g_ncand[NB];
__device__ int      g_rank[NB * CAND];
__device__ float    g_maxc[NB];

__device__ float    g_tsc[NB * 1024];
__device__ int      g_tcl[NB * 1024];
__device__ float    g_tx1[NB * 1024], g_ty1[NB * 1024], g_tx2[NB * 1024], g_ty2[NB * 1024];

__device__ unsigned      g_mask[NB * TOPK * 32];
__device__ unsigned char g_rnz[NB * TOPK];

struct Ptrs {
    const float* cls[5];
    const float* cnt[5];
    const float* reg[5];
};

// ---------------- XLA-compatible sigmoid (fma-free Horner, verified passing) ----------------
__device__ __forceinline__ float xla_tanh(float x) {
    float xc = fminf(fmaxf(x, -7.90531110763549805f), 7.90531110763549805f);
    float x2 = __fmul_rn(xc, xc);
    float p = -2.76076847742355e-16f;
    p = __fadd_rn(__fmul_rn(p, x2), 2.00018790482477e-13f);
    p = __fadd_rn(__fmul_rn(p, x2), -8.60467152213735e-11f);
    p = __fadd_rn(__fmul_rn(p, x2), 5.12229709037114e-08f);
    p = __fadd_rn(__fmul_rn(p, x2), 1.48572235717979e-05f);
    p = __fadd_rn(__fmul_rn(p, x2), 6.37261928875436e-04f);
    p = __fadd_rn(__fmul_rn(p, x2), 4.89352455891786e-03f);
    p = __fmul_rn(xc, p);
    float q = 1.19825839466702e-06f;
    q = __fadd_rn(__fmul_rn(q, x2), 1.18534705686654e-04f);
    q = __fadd_rn(__fmul_rn(q, x2), 2.26843463243900e-03f);
    q = __fadd_rn(__fmul_rn(q, x2), 4.89352518554385e-03f);
    float r = __fdiv_rn(p, q);
    return (fabsf(x) < 0.0004f) ? x : r;
}
__device__ __forceinline__ float xla_sigmoid(float x) {
    return __fadd_rn(0.5f, __fmul_rn(0.5f, xla_tanh(__fmul_rn(0.5f, x))));
}

// ---------------- kernel 1: per-anchor scores / classes / boxes ----------------
__global__ void k_score(Ptrs P) {
    int t = blockIdx.x * blockDim.x + threadIdx.x;
    if (t >= NB * NANCH) return;
    int b = t / NANCH;
    int a = t - b * NANCH;

    int l, p;
    if (a < 10000)      { l = 0; p = a; }
    else if (a < 12500) { l = 1; p = a - 10000; }
    else if (a < 13125) { l = 2; p = a - 12500; }
    else if (a < 13294) { l = 3; p = a - 13125; }
    else                { l = 4; p = a - 13294; }

    const int wlv[5] = {100, 50, 25, 13, 7};
    const int hwv[5] = {10000, 2500, 625, 169, 49};
    const int stv[5] = {8, 16, 32, 64, 128};
    int w = wlv[l], HW = hwv[l], s = stv[l];
    int y = p / w, x = p - y * w;
    float cx = (float)(x * s + (s >> 1));
    float cy = (float)(y * s + (s >> 1));

    const float* cls = P.cls[l];
    const float* cnt = P.cnt[l];
    const float* reg = P.reg[l];

    // argmax over sigmoid == argmax over logits (monotone). Track top-2 logits,
    // apply exact JAX first-occurrence semantics on their sigmoids.
    float ninf = -__int_as_float(0x7f800000);
    float m1 = ninf, m2 = ninf;
    int i1 = 0, i2 = 0;
    const float* cp = cls + (size_t)b * NCLS * HW + p;
#pragma unroll 8
    for (int c = 0; c < NCLS; c++) {
        float v = __ldg(cp + (size_t)c * HW);
        if (v > m1) { m2 = m1; i2 = i1; m1 = v; i1 = c; }
        else if (v > m2) { m2 = v; i2 = c; }
    }
    float s1 = xla_sigmoid(m1);
    float s2 = xla_sigmoid(m2);
    float best = s1;
    int bi = i1;
    if (s2 > s1 || (s2 == s1 && i2 < i1)) { best = fmaxf(s1, s2); bi = i2; }
    float cv = xla_sigmoid(__ldg(cnt + (size_t)b * HW + p));
    float score = sqrtf(__fmul_rn(best, cv));

    int o = b * NANCH + a;
    g_sbits[o] = __float_as_uint(score);
    g_cls[o] = bi + 1;

    float r0 = __ldg(reg + ((size_t)b * 4 + 0) * HW + p);
    float r1 = __ldg(reg + ((size_t)b * 4 + 1) * HW + p);
    float r2 = __ldg(reg + ((size_t)b * 4 + 2) * HW + p);
    float r3 = __ldg(reg + ((size_t)b * 4 + 3) * HW + p);
    g_bx1[o] = __fsub_rn(cx, r0);
    g_by1[o] = __fsub_rn(cy, r1);
    g_bx2[o] = __fadd_rn(cx, r2);
    g_by2[o] = __fadd_rn(cy, r3);
}

// ---------------- kernel 2a: per-batch radix select threshold + compact candidates ----------------
__global__ __launch_bounds__(1024) void k_select() {
    __shared__ unsigned s_hist[1024];
    __shared__ unsigned s_wsum[32];
    __shared__ unsigned s_B, s_above, s_cnt;

    int b = blockIdx.x;
    int tid = threadIdx.x;
    int lane = tid & 31, wid = tid >> 5;
    const unsigned* sb = g_sbits + b * NANCH;

    // zero rank array for this batch (re-zeroed every replay before k_rank's atomics)
    g_rank[b * CAND + tid] = 0;
    g_rank[b * CAND + 1024 + tid] = 0;

    // 3-pass 10-bit radix on positive-float bits -> bits of the 1000th-largest.
    // (scores in [0,1] -> bit patterns < 2^30, so 30 bits are exact.)
    unsigned prefix = 0;
    unsigned target = TOPK;
    for (int pass = 0; pass < 3; pass++) {
        int shift = 20 - 10 * pass;
        s_hist[tid] = 0;
        __syncthreads();
        for (int i = tid; i < NANCH; i += 1024) {
            unsigned v = sb[i];
            bool in = (pass == 0) || ((v >> (shift + 10)) == prefix);
            if (in) atomicAdd(&s_hist[(v >> shift) & 1023], 1u);
        }
        __syncthreads();
        unsigned h = s_hist[tid];
        // inclusive suffix sum: warp shuffles then cross-warp.
        unsigned v = h;
#pragma unroll
        for (int off = 1; off < 32; off <<= 1) {
            unsigned u = __shfl_down_sync(0xffffffffu, v, off);
            if (lane + off < 32) v += u;
        }
        if (lane == 0) s_wsum[wid] = v;
        __syncthreads();
        if (tid < 32) {
            unsigned wv = s_wsum[tid];
            unsigned acc = wv;
#pragma unroll
            for (int off = 1; off < 32; off <<= 1) {
                unsigned u = __shfl_down_sync(0xffffffffu, acc, off);
                if (tid + off < 32) acc += u;
            }
            s_wsum[tid] = acc - wv;  // exclusive suffix of warp totals
        }
        __syncthreads();
        unsigned S = v + s_wsum[wid];
        unsigned nxt = S - h;
        if (S >= target && nxt < target) { s_B = tid; s_above = nxt; }
        __syncthreads();
        prefix = (prefix << 10) | s_B;
        target = target - s_above;
        __syncthreads();
    }
    unsigned T = prefix;

    if (tid == 0) s_cnt = 0;
    __syncthreads();
    for (int i = tid; i < NANCH; i += 1024) {
        unsigned v = sb[i];
        if (v >= T) {
            unsigned pos = atomicAdd(&s_cnt, 1u);
            if (pos < CAND)
                g_cand[b * CAND + pos] = ((unsigned long long)v << 32) | (unsigned)(~i);
        }
    }
    __syncthreads();
    if (tid == 0) g_ncand[b] = (int)min(s_cnt, (unsigned)CAND);
}

// ---------------- kernel 2b: chip-parallel segment rank-by-count ----------------
// rank(key) = #(keys > key); keys distinct ((bits,~idx)), ties by smaller idx ==
// jax.lax.top_k stable order. Block (s,b): compare all candidates vs segment s.
__global__ __launch_bounds__(256) void k_rank() {
    __shared__ unsigned long long skey[SEGW];
    int b = blockIdx.y;
    int s = blockIdx.x;
    int tid = threadIdx.x;
    int n = g_ncand[b];
    int s0 = s * SEGW;
    int sn = n - s0;
    if (sn <= 0) return;
    if (sn > SEGW) sn = SEGW;
    if (tid < SEGW)
        skey[tid] = (tid < sn) ? g_cand[b * CAND + s0 + tid] : 0ULL;
    __syncthreads();

    for (int t = tid; t < n; t += 256) {
        unsigned long long k = g_cand[b * CAND + t];
        int cnt = 0;
        for (int j = 0; j < sn; j++)
            cnt += (skey[j] > k);
        if (cnt) atomicAdd(&g_rank[b * CAND + t], cnt);
    }
}

// ---------------- kernel 2c: gather by rank + max_coord ----------------
__global__ __launch_bounds__(1024) void k_gather() {
    __shared__ float s_red[32];
    int b = blockIdx.x;
    int tid = threadIdx.x;
    int lane = tid & 31, wid = tid >> 5;
    int n = g_ncand[b];

    float mloc = -__int_as_float(0x7f800000);
#pragma unroll
    for (int rp = 0; rp < 2; rp++) {
        int t = tid + rp * 1024;
        if (t < n) {
            int rk = g_rank[b * CAND + t];
            if (rk < TOPK) {
                unsigned long long key = g_cand[b * CAND + t];
                unsigned sbits = (unsigned)(key >> 32);
                int idx = (int)(~(unsigned)key);
                float sc = __uint_as_float(sbits);
                int o = b * NANCH + idx;
                int cl = g_cls[o];
                float x1 = g_bx1[o], y1 = g_by1[o], x2 = g_bx2[o], y2 = g_by2[o];
                int to = b * 1024 + rk;
                g_tsc[to] = sc; g_tcl[to] = cl;
                g_tx1[to] = x1; g_ty1[to] = y1; g_tx2[to] = x2; g_ty2[to] = y2;
                bool valid = (sc >= 0.05f);
                float m = valid ? fmaxf(fmaxf(x1, y1), fmaxf(x2, y2)) : 0.0f;
                mloc = fmaxf(mloc, m);
            }
        }
    }
#pragma unroll
    for (int o = 16; o > 0; o >>= 1) mloc = fmaxf(mloc, __shfl_down_sync(0xffffffffu, mloc, o));
    if (lane == 0) s_red[wid] = mloc;
    __syncthreads();
    if (tid < 32) {
        float v = s_red[tid];
#pragma unroll
        for (int o = 16; o > 0; o >>= 1) v = fmaxf(v, __shfl_down_sync(0xffffffffu, v, o));
        if (tid == 0) g_maxc[b] = v;
    }
}

// ---------------- kernel 3a: suppression bitmask (offset/area fused into preamble) ----------------
__global__ __launch_bounds__(256) void k_mask() {
    __shared__ float sx1[TOPK], sy1[TOPK], sx2[TOPK], sy2[TOPK], sar[TOPK];
    int b = blockIdx.y;
    int tid = threadIdx.x;
    int lane = tid & 31, wrp = tid >> 5;
    int base = b * 1024;
    float maxc = g_maxc[b];

    for (int idx = tid; idx < TOPK; idx += 256) {
        float off = __fmul_rn((float)g_tcl[base + idx], __fadd_rn(maxc, 1.0f));
        float ox1 = __fadd_rn(g_tx1[base + idx], off);
        float oy1 = __fadd_rn(g_ty1[base + idx], off);
        float ox2 = __fadd_rn(g_tx2[base + idx], off);
        float oy2 = __fadd_rn(g_ty2[base + idx], off);
        sx1[idx] = ox1; sy1[idx] = oy1; sx2[idx] = ox2; sy2[idx] = oy2;
        sar[idx] = __fmul_rn(__fadd_rn(__fsub_rn(ox2, ox1), 1.0f),
                             __fadd_rn(__fsub_rn(oy2, oy1), 1.0f));
    }
    __syncthreads();

    int i = blockIdx.x * 8 + wrp;   // 125 * 8 = 1000 rows
    if (i >= TOPK) return;
    float x1i = sx1[i], y1i = sy1[i], x2i = sx2[i], y2i = sy2[i], ai = sar[i];

    unsigned rowor = 0;
#pragma unroll 4
    for (int w = 0; w < 32; w++) {
        int j = w * 32 + lane;
        unsigned bit = 0;
        if (j > i && j < TOPK) {
            float xx1 = fmaxf(x1i, sx1[j]);
            float yy1 = fmaxf(y1i, sy1[j]);
            float xx2 = fminf(x2i, sx2[j]);
            float yy2 = fminf(y2i, sy2[j]);
            float iw = fmaxf(__fsub_rn(xx2, xx1), 0.0f);
            float ih = fmaxf(__fsub_rn(yy2, yy1), 0.0f);
            float inter = __fmul_rn(iw, ih);
            float uni = __fsub_rn(__fadd_rn(ai, sar[j]), inter);
            float iou = __fdiv_rn(inter, uni);
            bit = (iou > 0.6f) ? 1u : 0u;
        }
        unsigned word = __ballot_sync(0xffffffffu, bit);
        if (lane == 0) {
            g_mask[(b * TOPK + i) * 32 + w] = word;
            rowor |= word;
        }
    }
    if (lane == 0) g_rnz[b * TOPK + i] = (rowor != 0) ? 1 : 0;
}

// ---------------- kernel 3b: sparse greedy scan + output ----------------
__global__ __launch_bounds__(256) void k_scan(float* out) {
    __shared__ unsigned s_valid[32], s_ne[32];
    __shared__ volatile unsigned s_removed[32];

    int b = blockIdx.x;
    int tid = threadIdx.x;
    int lane = tid & 31;

    for (int k = 0; k < 4; k++) {
        int t = k * 256 + tid;
        int v = 0, nz = 0;
        if (t < TOPK) {
            v = (g_tsc[b * 1024 + t] >= 0.05f) ? 1 : 0;
            nz = g_rnz[b * TOPK + t];
        }
        unsigned bv = __ballot_sync(0xffffffffu, v);
        unsigned bn = __ballot_sync(0xffffffffu, nz);
        if (lane == 0 && t < TOPK) { s_valid[t >> 5] = bv; s_ne[t >> 5] = bn; }
    }
    if (tid < 32) s_removed[tid] = 0;
    __syncthreads();

    // warp 0: greedy scan over valid & nonempty rows, ascending (rows set bits j>i only)
    if (tid < 32) {
        for (int w = 0; w < 32; ++w) {
            unsigned cand = s_valid[w] & s_ne[w];
            while (true) {
                unsigned rm = s_removed[w];
                unsigned act = cand & ~rm;
                if (!act) break;
                int bp = __ffs(act) - 1;
                cand &= ~(1u << bp);
                int i = w * 32 + bp;
                unsigned mrow = g_mask[(b * TOPK + i) * 32 + lane];
                s_removed[lane] = s_removed[lane] | mrow;
                __syncwarp();
            }
        }
    }
    __syncthreads();

    // outputs: scores | classes | boxes
    for (int k = 0; k < 4; k++) {
        int t = k * 256 + tid;
        if (t < TOPK) {
            unsigned rem = s_removed[t >> 5];
            bool keep = (((s_valid[t >> 5] >> (t & 31)) & 1u) != 0u) &&
                        (((rem >> (t & 31)) & 1u) == 0u);
            int to = b * 1024 + t;
            float sc = keep ? g_tsc[to] : 0.0f;
            float cf = keep ? (float)g_tcl[to] : 0.0f;
            out[b * TOPK + t] = sc;
            out[NB * TOPK + b * TOPK + t] = cf;
            float bx1 = keep ? g_tx1[to] : 0.0f;
            float by1 = keep ? g_ty1[to] : 0.0f;
            float bx2 = keep ? g_tx2[to] : 0.0f;
            float by2 = keep ? g_ty2[to] : 0.0f;
            size_t bo = (size_t)2 * NB * TOPK + ((size_t)(b * TOPK + t)) * 4;
            out[bo + 0] = bx1;
            out[bo + 1] = by1;
            out[bo + 2] = bx2;
            out[bo + 3] = by2;
        }
    }
}

// ---------------- launch ----------------
extern "C" void kernel_launch(void* const* d_in, const int* in_sizes, int n_in,
                              void* d_out, int out_size) {
    (void)in_sizes; (void)n_in; (void)out_size;
    Ptrs P;
    for (int i = 0; i < 5; i++) {
        P.cls[i] = (const float*)d_in[i];
        P.cnt[i] = (const float*)d_in[5 + i];
        P.reg[i] = (const float*)d_in[10 + i];
    }
    int total = NB * NANCH;
    k_score<<<(total + 255) / 256, 256>>>(P);
    k_select<<<NB, 1024>>>();
    dim3 rg(NSEG, NB);
    k_rank<<<rg, 256>>>();
    k_gather<<<NB, 1024>>>();
    dim3 mg(125, NB);
    k_mask<<<mg, 256>>>();
    k_scan<<<NB, 256>>>((float*)d_out);
}